// round 15
// baseline (speedup 1.0000x reference)
#include <cuda_runtime.h>
#include <cstdint>

// ---------------------------------------------------------------------------
// Problem constants
//   B=32, T=2048, C=256, H=256, STRIDE=2, TC=1024, NC1=100, NC2=90
// ---------------------------------------------------------------------------
#define TCON 1024
typedef unsigned long long u64;

// LSTM smem: weights 32 rows x 256 = 8192 floats; h: 32 x 268 = 8576; stage 256
#define LSTM_SW_FLOATS 8192
#define LSTM_SH_FLOATS (32 * 268)
#define LSTM_SN_OFF (LSTM_SW_FLOATS + LSTM_SH_FLOATS)
#define LSTM_SMEM ((LSTM_SW_FLOATS + LSTM_SH_FLOATS + 256) * 4)   // 68096 B

// ---------------------------------------------------------------------------
// Scratch (device globals; no runtime allocation allowed)
// ---------------------------------------------------------------------------
__device__ float g_y[32768 * 256];
__device__ float g_pre_f[33554432];     // 32768*1024
__device__ float g_pre_r[33554432];
__device__ float g_h0[16777216];        // 32768*512
__device__ float g_h1[16777216];
__device__ float g_fc_part[32 * 192 * 32];
// Monotone step counters, one 128B line each (no false sharing between dirs).
__device__ __align__(128) unsigned int g_cnt_f[32];
__device__ __align__(128) unsigned int g_cnt_r[32];
__device__ __align__(128) unsigned int g_ecnt[32];

// ---------------------------------------------------------------------------
// Helpers
// ---------------------------------------------------------------------------
__device__ __forceinline__ void fma2(u64& acc, u64 a, u64 b) {
    asm("fma.rn.f32x2 %0, %1, %2, %0;" : "+l"(acc) : "l"(a), "l"(b));
}
__device__ __forceinline__ float2 u2f2(u64 v) {
    float2 r;
    asm("mov.b64 {%0,%1}, %2;" : "=f"(r.x), "=f"(r.y) : "l"(v));
    return r;
}
__device__ __forceinline__ u64 dup2(float a) {
    u64 r;
    asm("mov.b64 %0, {%1,%1};" : "=l"(r) : "f"(a));
    return r;
}
__device__ __forceinline__ float sigf(float x) {
    return __fdividef(1.f, 1.f + __expf(-x));
}
__device__ __forceinline__ float tanh_fast(float x) {
    return 2.f * sigf(2.f * x) - 1.f;
}
__device__ __forceinline__ unsigned ld_acq(const unsigned* p) {
    unsigned v;
    asm volatile("ld.acquire.gpu.global.u32 %0, [%1];" : "=r"(v) : "l"(p) : "memory");
    return v;
}
__device__ __forceinline__ void st_rlx(unsigned* p, unsigned v) {
    asm volatile("st.relaxed.gpu.global.u32 [%0], %1;" :: "l"(p), "r"(v) : "memory");
}
__device__ __forceinline__ void red_rel_add(unsigned* p, unsigned v) {
    asm volatile("red.release.gpu.global.add.u32 [%0], %1;" :: "l"(p), "r"(v) : "memory");
}
__device__ __forceinline__ unsigned atom_inc_acqrel(unsigned* p) {
    unsigned o;
    asm volatile("atom.add.acq_rel.gpu.global.u32 %0, [%1], 1;" : "=r"(o) : "l"(p) : "memory");
    return o;
}

// ---------------------------------------------------------------------------
// Conv1d(k=3, stride=2, pad=1) + BN(affine, eval) + ReLU
// ---------------------------------------------------------------------------
__global__ void conv_bn(const float* __restrict__ x,
                        const float* __restrict__ cw,
                        const float* __restrict__ cb,
                        const float* __restrict__ gmm,
                        const float* __restrict__ bet,
                        const float* __restrict__ mean,
                        const float* __restrict__ var) {
    int tb = blockIdx.x;
    int t = tb >> 5, b = tb & 31;
    int c = threadIdx.x;
    float w0 = cw[c * 3 + 0], w1 = cw[c * 3 + 1], w2 = cw[c * 3 + 2];
    const float* xb = x + b * 2048;
    int xi = t * 2;
    float xm1 = (xi >= 1) ? xb[xi - 1] : 0.f;
    float x0 = xb[xi];
    float xp1 = xb[xi + 1];
    float conv = fmaf(xm1, w0, fmaf(x0, w1, xp1 * w2)) + cb[c];
    float inv = gmm[c] * rsqrtf(var[c] + 1e-5f);
    float v = conv * inv + (bet[c] - mean[c] * inv);
    g_y[(size_t)tb * 256 + c] = fmaxf(v, 0.f);
}

// ---------------------------------------------------------------------------
// SGEMM (TN): C[M=32768][N=1024] = A[M][K] * B[N][K]^T + bias[N]
// 128x128 block tile, BK=8, 256 threads, 8x8 micro-tile, f32x2-packed FMAs.
// ---------------------------------------------------------------------------
__global__ void __launch_bounds__(256) sgemm_tn(const float* __restrict__ A,
                                                const float* __restrict__ B,
                                                const float* __restrict__ bias,
                                                float* __restrict__ C,
                                                int K) {
    __shared__ __align__(16) float As[8][132];
    __shared__ __align__(16) float Bs[8][132];
    int bm = blockIdx.y * 128;
    int bn = blockIdx.x * 128;
    int tid = threadIdx.x;
    int tx = tid & 15, ty = tid >> 4;
    int lrow = tid >> 1;
    int lk = (tid & 1) * 4;
    const float* Ap = A + (size_t)(bm + lrow) * K + lk;
    const float* Bp = B + (size_t)(bn + lrow) * K + lk;

    u64 acc2[8][4];
#pragma unroll
    for (int i = 0; i < 8; i++)
#pragma unroll
        for (int j = 0; j < 4; j++) acc2[i][j] = 0ull;

    for (int k0 = 0; k0 < K; k0 += 8) {
        float4 av = *(const float4*)(Ap + k0);
        float4 bv = *(const float4*)(Bp + k0);
        __syncthreads();
        As[lk + 0][lrow] = av.x; As[lk + 1][lrow] = av.y;
        As[lk + 2][lrow] = av.z; As[lk + 3][lrow] = av.w;
        Bs[lk + 0][lrow] = bv.x; Bs[lk + 1][lrow] = bv.y;
        Bs[lk + 2][lrow] = bv.z; Bs[lk + 3][lrow] = bv.w;
        __syncthreads();
#pragma unroll
        for (int kk = 0; kk < 8; kk++) {
            float a[8];
            *(float4*)&a[0] = *(const float4*)&As[kk][ty * 8];
            *(float4*)&a[4] = *(const float4*)&As[kk][ty * 8 + 4];
            ulonglong2 bl = *(const ulonglong2*)&Bs[kk][tx * 8];
            ulonglong2 bh = *(const ulonglong2*)&Bs[kk][tx * 8 + 4];
            u64 b2[4] = {bl.x, bl.y, bh.x, bh.y};
#pragma unroll
            for (int i = 0; i < 8; i++) {
                u64 a2 = dup2(a[i]);
#pragma unroll
                for (int j2 = 0; j2 < 4; j2++) fma2(acc2[i][j2], a2, b2[j2]);
            }
        }
    }
#pragma unroll
    for (int i = 0; i < 8; i++) {
        size_t m = (size_t)(bm + ty * 8 + i);
        int n = bn + tx * 8;
        float2 p0 = u2f2(acc2[i][0]);
        float2 p1 = u2f2(acc2[i][1]);
        float2 p2 = u2f2(acc2[i][2]);
        float2 p3 = u2f2(acc2[i][3]);
        float4 o0, o1;
        o0.x = p0.x + bias[n + 0]; o0.y = p0.y + bias[n + 1];
        o0.z = p1.x + bias[n + 2]; o0.w = p1.y + bias[n + 3];
        o1.x = p2.x + bias[n + 4]; o1.y = p2.y + bias[n + 5];
        o1.z = p3.x + bias[n + 6]; o1.w = p3.y + bias[n + 7];
        *(float4*)&C[m * 1024 + n] = o0;
        *(float4*)&C[m * 1024 + n + 4] = o1;
    }
}

// ---------------------------------------------------------------------------
// BiLSTM recurrence (one layer, both directions).
// 64 blocks x 256 threads. blocks [0,32): forward, [32,64): reverse.
// Block covers j in [jg*8, jg*8+8). Warp = jj (one j), lane = batch b (0..31).
// Per-direction sync domain: 32 blocks (halved vs R11 -> less skew, fewer
// pollers); 8 warps/block = 2 per SMSP (latency hiding in GEMV + repack).
// Exchange identical in spirit to R11: staged smem -> coalesced STG by warp 0,
// coalesced LDG repack spread over all 8 warps.
// Cross-block sync: monotone counter, red.release arrival + ld.acquire poll.
// ---------------------------------------------------------------------------
__global__ void __launch_bounds__(256) lstm_layer(const float* __restrict__ pre_fw,
                                                  const float* __restrict__ pre_rv,
                                                  const float* __restrict__ whh_fw,
                                                  const float* __restrict__ whh_rv,
                                                  float* __restrict__ hout) {
    extern __shared__ float smem[];
    float* sw = smem;                      // [ljj*4+g][256], ljj in 0..7
    float* shh = smem + LSTM_SW_FLOATS;    // [b][268]
    float* snew = smem + LSTM_SN_OFF;      // [b*8 + jj]

    const int tid = threadIdx.x;
    const int dir = blockIdx.x >> 5;
    const int jg = blockIdx.x & 31;
    const int jj = tid >> 5;               // warp id = local j (0..7)
    const int lane = tid & 31;             // lane = batch
    const int j = jg * 8 + jj;
    const float* whh = dir ? whh_rv : whh_fw;
    const float* pre = dir ? pre_rv : pre_fw;
    const int foff = dir ? 256 : 0;

    // Load W_hh slice: sw[(ljj*4+g)*256 + k] = whh[(g*256 + jg*8 + ljj)*256 + k]
    for (int i = tid; i < 8192; i += 256) {
        int row = i >> 8;                  // ljj*4+g (0..31)
        int k = i & 255;
        int ljj = row >> 2, g = row & 3;
        sw[row * 256 + k] = whh[((size_t)(g * 256 + jg * 8 + ljj)) * 256 + k];
    }
    for (int i = tid; i < LSTM_SH_FLOATS; i += 256) shh[i] = 0.f;
    __syncthreads();

    const float* hrow = shh + lane * 268;
    const float* wbase = sw + jj * 1024;   // this j's 4 gate rows x 256

    unsigned* cntp = dir ? &g_cnt_r[0] : &g_cnt_f[0];

    float c_state = 0.f;
    int t = dir ? (TCON - 1) : 0;

    // prefetch pre-activations for step 0
    const float* pr0 = pre + ((size_t)t * 32 + lane) * 1024 + j;
    float p_i = pr0[0], p_f = pr0[256], p_g = pr0[512], p_o = pr0[768];

    for (int step = 0; step < TCON; step++) {
        // ---- gate GEMV: acc[g] = sum_k W[g*256+j][k] * h[k][b] ----
        u64 a0 = 0ull, a1 = 0ull, a2 = 0ull, a3 = 0ull;
#pragma unroll 2
        for (int k4 = 0; k4 < 64; k4++) {
            ulonglong2 hv = *(const ulonglong2*)(hrow + k4 * 4);
            ulonglong2 w0 = *(const ulonglong2*)(wbase + k4 * 4);
            ulonglong2 w1 = *(const ulonglong2*)(wbase + 256 + k4 * 4);
            ulonglong2 w2 = *(const ulonglong2*)(wbase + 512 + k4 * 4);
            ulonglong2 w3 = *(const ulonglong2*)(wbase + 768 + k4 * 4);
            fma2(a0, w0.x, hv.x); fma2(a0, w0.y, hv.y);
            fma2(a1, w1.x, hv.x); fma2(a1, w1.y, hv.y);
            fma2(a2, w2.x, hv.x); fma2(a2, w2.y, hv.y);
            fma2(a3, w3.x, hv.x); fma2(a3, w3.y, hv.y);
        }
        float2 vi = u2f2(a0), vf = u2f2(a1), vg = u2f2(a2), vo = u2f2(a3);
        float gi = vi.x + vi.y + p_i;
        float gf = vf.x + vf.y + p_f;
        float gg = vg.x + vg.y + p_g;
        float go = vo.x + vo.y + p_o;
        float iv = sigf(gi), fv = sigf(gf), zv = tanh_fast(gg), ov = sigf(go);
        c_state = fv * c_state + iv * zv;
        float h_val = ov * tanh_fast(c_state);

        // stage h for the coalesced writer: snew[b][8j]
        snew[lane * 8 + jj] = h_val;

        int t_next = dir ? (t - 1) : (t + 1);
        if (step != TCON - 1) {
            // prefetch next step's pre-activations (independent of barrier)
            const float* prn = pre + ((size_t)t_next * 32 + lane) * 1024 + j;
            p_i = prn[0]; p_f = prn[256]; p_g = prn[512]; p_o = prn[768];
        }

        __syncthreads();                 // snew complete block-wide

        // ---- coalesced h store (warp 0): 2x STG.128 per lane ----
        if (jj == 0) {
            float4 v0 = *(const float4*)(snew + lane * 8);
            float4 v1 = *(const float4*)(snew + lane * 8 + 4);
            float* dst = &hout[((size_t)t * 32 + lane) * 512 + foff + jg * 8];
            *(float4*)dst = v0;
            *(float4*)(dst + 4) = v1;
            __syncwarp();
            if (lane == 0) {
                red_rel_add(cntp, 1u);   // publish stores; no return trip
                unsigned target = 32u * (unsigned)(step + 1);
                while (ld_acq(cntp) < target) {}
            }
        }
        __syncthreads();

        // ---- coalesced repack: warp jj loads batches jj*4..jj*4+3 ----
        if (step != TCON - 1) {
            const float* base = hout + ((size_t)t * 32) * 512 + foff;
            float4 tmp[8];
#pragma unroll
            for (int i = 0; i < 8; i++) {
                int b = jj * 4 + (i >> 1);
                int j0 = (i & 1) * 128 + lane * 4;
                tmp[i] = *(const float4*)(base + (size_t)b * 512 + j0);
            }
#pragma unroll
            for (int i = 0; i < 8; i++) {
                int b = jj * 4 + (i >> 1);
                int j0 = (i & 1) * 128 + lane * 4;
                *(float4*)(shh + b * 268 + j0) = tmp[i];
            }
        }
        __syncthreads();
        t = t_next;
    }

    // ---- epilogue: one-shot reset of counters for next launch / replay ----
    if (tid == 0) {
        unsigned old = atom_inc_acqrel(&g_ecnt[0]);
        if (old == 63u) {
            st_rlx(&g_cnt_f[0], 0u);
            st_rlx(&g_cnt_r[0], 0u);
            st_rlx(&g_ecnt[0], 0u);
        }
    }
}

// ---------------------------------------------------------------------------
// FC heads (split-k partials + deterministic reduce)
// ---------------------------------------------------------------------------
__global__ void __launch_bounds__(256) fc_main(const float* __restrict__ h,
                                               const float* __restrict__ w1,
                                               const float* __restrict__ w2) {
    extern __shared__ float sh[];
    int kc = blockIdx.x;
    int grp = blockIdx.y;
    int tid = threadIdx.x;
    int nl = tid >> 4, bb = tid & 15;
    int n = grp * 16 + nl;
    bool valid = (n < 190);
    const float* wrow = valid
        ? (n < 100 ? w1 + (size_t)n * 524288 : w2 + (size_t)(n - 100) * 524288)
        : w1;

    float ax = 0.f, ay = 0.f;
    for (int tt = 0; tt < 32; tt++) {
        int t = kc * 32 + tt;
        const float* slab = h + (size_t)t * 16384;
        __syncthreads();
        for (int i = tid; i < 4096; i += 256) {
            int b = i >> 7;
            int q = i & 127;
            float4 v = *(const float4*)&slab[b * 512 + q * 4];
            int bl = (b & 15) * 2 + (b >> 4);
            int f = q * 4;
            sh[(f + 0) * 32 + bl] = v.x;
            sh[(f + 1) * 32 + bl] = v.y;
            sh[(f + 2) * 32 + bl] = v.z;
            sh[(f + 3) * 32 + bl] = v.w;
        }
        __syncthreads();
        const float* wp = wrow + (size_t)t * 512;
#pragma unroll 4
        for (int f4 = 0; f4 < 128; f4++) {
            float4 wv = *(const float4*)(wp + f4 * 4);
            const float* s0 = sh + (f4 * 4) * 32 + bb * 2;
            float2 a0 = *(const float2*)(s0);
            float2 a1 = *(const float2*)(s0 + 32);
            float2 a2 = *(const float2*)(s0 + 64);
            float2 a3 = *(const float2*)(s0 + 96);
            ax = fmaf(wv.x, a0.x, ax); ay = fmaf(wv.x, a0.y, ay);
            ax = fmaf(wv.y, a1.x, ax); ay = fmaf(wv.y, a1.y, ay);
            ax = fmaf(wv.z, a2.x, ax); ay = fmaf(wv.z, a2.y, ay);
            ax = fmaf(wv.w, a3.x, ax); ay = fmaf(wv.w, a3.y, ay);
        }
    }
    if (valid) {
        g_fc_part[((size_t)kc * 192 + n) * 32 + bb] = ax;
        g_fc_part[((size_t)kc * 192 + n) * 32 + bb + 16] = ay;
    }
}

__global__ void fc_reduce(const float* __restrict__ b1,
                          const float* __restrict__ b2,
                          float* __restrict__ out) {
    int i = blockIdx.x * 256 + threadIdx.x;
    if (i >= 6080) return;
    int n = i >> 5;
    int b = i & 31;
    float s = (n < 100) ? b1[n] : b2[n - 100];
#pragma unroll
    for (int kc = 0; kc < 32; kc++)
        s += g_fc_part[((size_t)kc * 192 + n) * 32 + b];
    if (n < 100) out[b * 100 + n] = s;
    else out[3200 + b * 90 + (n - 100)] = s;
}

// ---------------------------------------------------------------------------
// Launch
// ---------------------------------------------------------------------------
extern "C" void kernel_launch(void* const* d_in, const int* in_sizes, int n_in,
                              void* d_out, int out_size) {
    const float* x       = (const float*)d_in[0];
    const float* conv_w  = (const float*)d_in[1];
    const float* conv_b  = (const float*)d_in[2];
    const float* bn_g    = (const float*)d_in[3];
    const float* bn_b    = (const float*)d_in[4];
    const float* bn_m    = (const float*)d_in[5];
    const float* bn_v    = (const float*)d_in[6];
    const float* w_ih_f0 = (const float*)d_in[7];
    const float* w_hh_f0 = (const float*)d_in[8];
    const float* b_f0    = (const float*)d_in[9];
    const float* w_ih_r0 = (const float*)d_in[10];
    const float* w_hh_r0 = (const float*)d_in[11];
    const float* b_r0    = (const float*)d_in[12];
    const float* w_ih_f1 = (const float*)d_in[13];
    const float* w_hh_f1 = (const float*)d_in[14];
    const float* b_f1    = (const float*)d_in[15];
    const float* w_ih_r1 = (const float*)d_in[16];
    const float* w_hh_r1 = (const float*)d_in[17];
    const float* b_r1    = (const float*)d_in[18];
    const float* fc1_w   = (const float*)d_in[19];
    const float* fc1_b   = (const float*)d_in[20];
    const float* fc2_w   = (const float*)d_in[21];
    const float* fc2_b   = (const float*)d_in[22];
    float* out = (float*)d_out;

    float *py, *ppf, *ppr, *ph0, *ph1;
    cudaGetSymbolAddress((void**)&py, g_y);
    cudaGetSymbolAddress((void**)&ppf, g_pre_f);
    cudaGetSymbolAddress((void**)&ppr, g_pre_r);
    cudaGetSymbolAddress((void**)&ph0, g_h0);
    cudaGetSymbolAddress((void**)&ph1, g_h1);

    cudaFuncSetAttribute(lstm_layer, cudaFuncAttributeMaxDynamicSharedMemorySize, LSTM_SMEM);
    cudaFuncSetAttribute(fc_main, cudaFuncAttributeMaxDynamicSharedMemorySize, 65536);

    // 1) conv + bn + relu
    conv_bn<<<32768, 256>>>(x, conv_w, conv_b, bn_g, bn_b, bn_m, bn_v);

    // 2) layer 0 input projections (K=256)
    dim3 gg(8, 256);
    sgemm_tn<<<gg, 256>>>(py, w_ih_f0, b_f0, ppf, 256);
    sgemm_tn<<<gg, 256>>>(py, w_ih_r0, b_r0, ppr, 256);

    // 3) layer 0 recurrence (32 blocks/dir x 8 warps)
    lstm_layer<<<64, 256, LSTM_SMEM>>>(ppf, ppr, w_hh_f0, w_hh_r0, ph0);

    // 4) layer 1 input projections (K=512)
    sgemm_tn<<<gg, 256>>>(ph0, w_ih_f1, b_f1, ppf, 512);
    sgemm_tn<<<gg, 256>>>(ph0, w_ih_r1, b_r1, ppr, 512);

    // 5) layer 1 recurrence
    lstm_layer<<<64, 256, LSTM_SMEM>>>(ppf, ppr, w_hh_f1, w_hh_r1, ph1);

    // 6) FC heads
    dim3 fg(32, 12);
    fc_main<<<fg, 256, 65536>>>(ph1, fc1_w, fc2_w);
    fc_reduce<<<24, 256>>>(fc1_b, fc2_b, out);
}

// round 16
// speedup vs baseline: 1.2257x; 1.2257x over previous
#include <cuda_runtime.h>
#include <cuda_bf16.h>
#include <cstdint>

// ---------------------------------------------------------------------------
// Problem constants
//   B=32, T=2048, C=256, H=256, STRIDE=2, TC=1024, NC1=100, NC2=90
// ---------------------------------------------------------------------------
#define TCON 1024
typedef unsigned long long u64;

// LSTM smem: weights 16x256 = 4096 floats; h: 32x268 = 8576; stage: 128
#define LSTM_SW_FLOATS 4096
#define LSTM_SH_FLOATS (32 * 268)
#define LSTM_SN_OFF (LSTM_SW_FLOATS + LSTM_SH_FLOATS)
#define LSTM_SMEM ((LSTM_SW_FLOATS + LSTM_SH_FLOATS + 128) * 4)

// ---------------------------------------------------------------------------
// Scratch (device globals; no runtime allocation allowed)
// ---------------------------------------------------------------------------
__device__ float g_y[32768 * 256];
__device__ float g_pre_f[33554432];     // 32768*1024
__device__ float g_pre_r[33554432];
__device__ float g_h0[16777216];        // 32768*512
__device__ float g_h1[16777216];
__device__ float g_fc_part[32 * 192 * 32];
// Monotone step counters, one 128B line each (no false sharing between dirs).
__device__ __align__(128) unsigned int g_cnt_f[32];
__device__ __align__(128) unsigned int g_cnt_r[32];
__device__ __align__(128) unsigned int g_ecnt[32];

// ---------------------------------------------------------------------------
// Helpers
// ---------------------------------------------------------------------------
__device__ __forceinline__ void fma2(u64& acc, u64 a, u64 b) {
    asm("fma.rn.f32x2 %0, %1, %2, %0;" : "+l"(acc) : "l"(a), "l"(b));
}
__device__ __forceinline__ float2 u2f2(u64 v) {
    float2 r;
    asm("mov.b64 {%0,%1}, %2;" : "=f"(r.x), "=f"(r.y) : "l"(v));
    return r;
}
__device__ __forceinline__ float sigf(float x) {
    return __fdividef(1.f, 1.f + __expf(-x));
}
__device__ __forceinline__ float tanh_fast(float x) {
    return 2.f * sigf(2.f * x) - 1.f;
}
__device__ __forceinline__ unsigned ld_acq(const unsigned* p) {
    unsigned v;
    asm volatile("ld.acquire.gpu.global.u32 %0, [%1];" : "=r"(v) : "l"(p) : "memory");
    return v;
}
__device__ __forceinline__ void st_rlx(unsigned* p, unsigned v) {
    asm volatile("st.relaxed.gpu.global.u32 [%0], %1;" :: "l"(p), "r"(v) : "memory");
}
__device__ __forceinline__ void red_rel_add(unsigned* p, unsigned v) {
    asm volatile("red.release.gpu.global.add.u32 [%0], %1;" :: "l"(p), "r"(v) : "memory");
}
__device__ __forceinline__ unsigned atom_inc_acqrel(unsigned* p) {
    unsigned o;
    asm volatile("atom.add.acq_rel.gpu.global.u32 %0, [%1], 1;" : "=r"(o) : "l"(p) : "memory");
    return o;
}
__device__ __forceinline__ uint32_t smem_u32(const void* p) {
    uint32_t a;
    asm("{ .reg .u64 t; cvta.to.shared.u64 t, %1; cvt.u32.u64 %0, t; }"
        : "=r"(a) : "l"(p));
    return a;
}
__device__ __forceinline__ void ldm4(uint32_t& d0, uint32_t& d1, uint32_t& d2,
                                     uint32_t& d3, uint32_t addr) {
    asm volatile("ldmatrix.sync.aligned.m8n8.x4.shared.b16 {%0,%1,%2,%3}, [%4];"
                 : "=r"(d0), "=r"(d1), "=r"(d2), "=r"(d3) : "r"(addr));
}
__device__ __forceinline__ void mma_bf16(float* c, const uint32_t* a,
                                         uint32_t b0, uint32_t b1) {
    asm volatile(
        "mma.sync.aligned.m16n8k16.row.col.f32.bf16.bf16.f32 "
        "{%0,%1,%2,%3}, {%4,%5,%6,%7}, {%8,%9}, {%0,%1,%2,%3};"
        : "+f"(c[0]), "+f"(c[1]), "+f"(c[2]), "+f"(c[3])
        : "r"(a[0]), "r"(a[1]), "r"(a[2]), "r"(a[3]), "r"(b0), "r"(b1));
}

// ---------------------------------------------------------------------------
// Conv1d(k=3, stride=2, pad=1) + BN(affine, eval) + ReLU
// ---------------------------------------------------------------------------
__global__ void conv_bn(const float* __restrict__ x,
                        const float* __restrict__ cw,
                        const float* __restrict__ cb,
                        const float* __restrict__ gmm,
                        const float* __restrict__ bet,
                        const float* __restrict__ mean,
                        const float* __restrict__ var) {
    int tb = blockIdx.x;
    int t = tb >> 5, b = tb & 31;
    int c = threadIdx.x;
    float w0 = cw[c * 3 + 0], w1 = cw[c * 3 + 1], w2 = cw[c * 3 + 2];
    const float* xb = x + b * 2048;
    int xi = t * 2;
    float xm1 = (xi >= 1) ? xb[xi - 1] : 0.f;
    float x0 = xb[xi];
    float xp1 = xb[xi + 1];
    float conv = fmaf(xm1, w0, fmaf(x0, w1, xp1 * w2)) + cb[c];
    float inv = gmm[c] * rsqrtf(var[c] + 1e-5f);
    float v = conv * inv + (bet[c] - mean[c] * inv);
    g_y[(size_t)tb * 256 + c] = fmaxf(v, 0.f);
}

// ---------------------------------------------------------------------------
// Tensor-core GEMM (TN), 3-pass bf16 hi/lo split (error ~2^-17):
//   C[M][N=1024] = A[M][K] * B[N][K]^T + bias[N]
// Block tile 128x64xBK32, 256 threads, 8 warps (4x2), warp tile 32x32.
// fp32 operands split into (hi, lo) bf16 during SMEM store; mainloop does
// hi*hi + hi*lo + lo*hi with fp32 accumulators (mma.m16n8k16).
// SMEM rows padded to 40 bf16 (80 B) -> ldmatrix conflict-free.
// ---------------------------------------------------------------------------
#define GA_HI 0
#define GA_LO 5120
#define GB_HI 10240
#define GB_LO 12800

__global__ void __launch_bounds__(256) gemm_bf16x3(const float* __restrict__ A,
                                                   const float* __restrict__ B,
                                                   const float* __restrict__ bias,
                                                   float* __restrict__ C,
                                                   int K) {
    __shared__ __align__(16) __nv_bfloat16 sm[15360];
    const int tid = threadIdx.x;
    const int bn = blockIdx.x * 64;
    const int bm = blockIdx.y * 128;
    const int lane = tid & 31;
    const int w = tid >> 5;
    const int wm = w >> 1, wn = w & 1;
    const uint32_t sbase = smem_u32(sm);

    float acc[2][4][4];
#pragma unroll
    for (int i = 0; i < 2; i++)
#pragma unroll
        for (int j = 0; j < 4; j++)
#pragma unroll
            for (int e = 0; e < 4; e++) acc[i][j][e] = 0.f;

    const int KIT = K >> 5;
    float4 ra[4], rb[2];

    // initial global load (k0 = 0)
#pragma unroll
    for (int q = 0; q < 4; q++) {
        int idx = tid * 4 + q, r = idx >> 3, c = idx & 7;
        ra[q] = *(const float4*)&A[(size_t)(bm + r) * K + c * 4];
    }
#pragma unroll
    for (int q = 0; q < 2; q++) {
        int idx = tid * 2 + q, r = idx >> 3, c = idx & 7;
        rb[q] = *(const float4*)&B[(size_t)(bn + r) * K + c * 4];
    }

    for (int it = 0; it < KIT; it++) {
        // ---- split-convert + STS ----
#pragma unroll
        for (int q = 0; q < 4; q++) {
            int idx = tid * 4 + q, r = idx >> 3, c = idx & 7;
            float f[4] = {ra[q].x, ra[q].y, ra[q].z, ra[q].w};
            __nv_bfloat162 h0, h1, l0, l1;
            __nv_bfloat16 h[4], l[4];
#pragma unroll
            for (int e = 0; e < 4; e++) {
                h[e] = __float2bfloat16(f[e]);
                l[e] = __float2bfloat16(f[e] - __bfloat162float(h[e]));
            }
            h0.x = h[0]; h0.y = h[1]; h1.x = h[2]; h1.y = h[3];
            l0.x = l[0]; l0.y = l[1]; l1.x = l[2]; l1.y = l[3];
            int el = r * 40 + c * 4;
            *(__nv_bfloat162*)&sm[GA_HI + el] = h0;
            *(__nv_bfloat162*)&sm[GA_HI + el + 2] = h1;
            *(__nv_bfloat162*)&sm[GA_LO + el] = l0;
            *(__nv_bfloat162*)&sm[GA_LO + el + 2] = l1;
        }
#pragma unroll
        for (int q = 0; q < 2; q++) {
            int idx = tid * 2 + q, r = idx >> 3, c = idx & 7;
            float f[4] = {rb[q].x, rb[q].y, rb[q].z, rb[q].w};
            __nv_bfloat162 h0, h1, l0, l1;
            __nv_bfloat16 h[4], l[4];
#pragma unroll
            for (int e = 0; e < 4; e++) {
                h[e] = __float2bfloat16(f[e]);
                l[e] = __float2bfloat16(f[e] - __bfloat162float(h[e]));
            }
            h0.x = h[0]; h0.y = h[1]; h1.x = h[2]; h1.y = h[3];
            l0.x = l[0]; l0.y = l[1]; l1.x = l[2]; l1.y = l[3];
            int el = r * 40 + c * 4;
            *(__nv_bfloat162*)&sm[GB_HI + el] = h0;
            *(__nv_bfloat162*)&sm[GB_HI + el + 2] = h1;
            *(__nv_bfloat162*)&sm[GB_LO + el] = l0;
            *(__nv_bfloat162*)&sm[GB_LO + el + 2] = l1;
        }
        __syncthreads();

        // prefetch next k-slab into regs (overlaps mma below)
        if (it + 1 < KIT) {
            int k0 = (it + 1) * 32;
#pragma unroll
            for (int q = 0; q < 4; q++) {
                int idx = tid * 4 + q, r = idx >> 3, c = idx & 7;
                ra[q] = *(const float4*)&A[(size_t)(bm + r) * K + k0 + c * 4];
            }
#pragma unroll
            for (int q = 0; q < 2; q++) {
                int idx = tid * 2 + q, r = idx >> 3, c = idx & 7;
                rb[q] = *(const float4*)&B[(size_t)(bn + r) * K + k0 + c * 4];
            }
        }

        // ---- compute: 2 chunks of k16 ----
        const int mat = lane >> 3, mr = lane & 7;
#pragma unroll
        for (int ck = 0; ck < 2; ck++) {
            int kof = ck * 16;
            uint32_t ah[2][4], al[2][4], bh[2][4], bl[2][4];
#pragma unroll
            for (int mi = 0; mi < 2; mi++) {
                int row = wm * 32 + mi * 16 + ((mat & 1) * 8 + mr);
                int col = kof + ((mat >> 1) * 8);
                uint32_t off = (uint32_t)(row * 40 + col) * 2;
                ldm4(ah[mi][0], ah[mi][1], ah[mi][2], ah[mi][3],
                     sbase + GA_HI * 2 + off);
                ldm4(al[mi][0], al[mi][1], al[mi][2], al[mi][3],
                     sbase + GA_LO * 2 + off);
            }
#pragma unroll
            for (int p = 0; p < 2; p++) {
                int row = wn * 32 + p * 16 + ((mat >> 1) * 8 + mr);
                int col = kof + ((mat & 1) * 8);
                uint32_t off = (uint32_t)(row * 40 + col) * 2;
                ldm4(bh[p][0], bh[p][1], bh[p][2], bh[p][3],
                     sbase + GB_HI * 2 + off);
                ldm4(bl[p][0], bl[p][1], bl[p][2], bl[p][3],
                     sbase + GB_LO * 2 + off);
            }
#pragma unroll
            for (int mi = 0; mi < 2; mi++)
#pragma unroll
                for (int ni = 0; ni < 4; ni++) {
                    int p = ni >> 1, o = (ni & 1) * 2;
                    mma_bf16(acc[mi][ni], ah[mi], bh[p][o], bh[p][o + 1]);
                    mma_bf16(acc[mi][ni], ah[mi], bl[p][o], bl[p][o + 1]);
                    mma_bf16(acc[mi][ni], al[mi], bh[p][o], bh[p][o + 1]);
                }
        }
        __syncthreads();
    }

    // ---- epilogue ----
    const int g = lane >> 2, tg = lane & 3;
#pragma unroll
    for (int mi = 0; mi < 2; mi++)
#pragma unroll
        for (int ni = 0; ni < 4; ni++) {
            int m0 = bm + wm * 32 + mi * 16 + g;
            int n0 = bn + wn * 32 + ni * 8 + tg * 2;
            float b0 = bias[n0], b1 = bias[n0 + 1];
            float2 v0, v1;
            v0.x = acc[mi][ni][0] + b0; v0.y = acc[mi][ni][1] + b1;
            v1.x = acc[mi][ni][2] + b0; v1.y = acc[mi][ni][3] + b1;
            *(float2*)&C[(size_t)m0 * 1024 + n0] = v0;
            *(float2*)&C[(size_t)(m0 + 8) * 1024 + n0] = v1;
        }
}

// ---------------------------------------------------------------------------
// BiLSTM recurrence (one layer, both directions). R11 configuration verbatim.
// 128 blocks x 128 threads. blocks [0,64): forward, [64,128): reverse.
// Block covers j in [jg*4, jg*4+4). Warp = jj (one j), lane = batch b (0..31).
// ---------------------------------------------------------------------------
__global__ void __launch_bounds__(128) lstm_layer(const float* __restrict__ pre_fw,
                                                  const float* __restrict__ pre_rv,
                                                  const float* __restrict__ whh_fw,
                                                  const float* __restrict__ whh_rv,
                                                  float* __restrict__ hout) {
    extern __shared__ float smem[];
    float* sw = smem;                      // [jj*4+g][256]
    float* shh = smem + LSTM_SW_FLOATS;    // [b][268]
    float* snew = smem + LSTM_SN_OFF;      // [b*4 + jj]

    const int tid = threadIdx.x;
    const int dir = blockIdx.x >> 6;
    const int jg = blockIdx.x & 63;
    const int jj = tid >> 5;               // warp id = local j
    const int lane = tid & 31;             // lane = batch
    const int j = jg * 4 + jj;
    const float* whh = dir ? whh_rv : whh_fw;
    const float* pre = dir ? pre_rv : pre_fw;
    const int foff = dir ? 256 : 0;

    for (int i = tid; i < 4096; i += 128) {
        int row = i >> 8;
        int k = i & 255;
        int ljj = row >> 2, g = row & 3;
        sw[row * 256 + k] = whh[((size_t)(g * 256 + jg * 4 + ljj)) * 256 + k];
    }
    for (int i = tid; i < LSTM_SH_FLOATS; i += 128) shh[i] = 0.f;
    __syncthreads();

    const float* hrow = shh + lane * 268;
    const float* wbase = sw + jj * 1024;

    unsigned* cntp = dir ? &g_cnt_r[0] : &g_cnt_f[0];

    float c_state = 0.f;
    int t = dir ? (TCON - 1) : 0;

    const float* pr0 = pre + ((size_t)t * 32 + lane) * 1024 + j;
    float p_i = pr0[0], p_f = pr0[256], p_g = pr0[512], p_o = pr0[768];

    for (int step = 0; step < TCON; step++) {
        u64 a0 = 0ull, a1 = 0ull, a2 = 0ull, a3 = 0ull;
#pragma unroll 2
        for (int k4 = 0; k4 < 64; k4++) {
            ulonglong2 hv = *(const ulonglong2*)(hrow + k4 * 4);
            ulonglong2 w0 = *(const ulonglong2*)(wbase + k4 * 4);
            ulonglong2 w1 = *(const ulonglong2*)(wbase + 256 + k4 * 4);
            ulonglong2 w2 = *(const ulonglong2*)(wbase + 512 + k4 * 4);
            ulonglong2 w3 = *(const ulonglong2*)(wbase + 768 + k4 * 4);
            fma2(a0, w0.x, hv.x); fma2(a0, w0.y, hv.y);
            fma2(a1, w1.x, hv.x); fma2(a1, w1.y, hv.y);
            fma2(a2, w2.x, hv.x); fma2(a2, w2.y, hv.y);
            fma2(a3, w3.x, hv.x); fma2(a3, w3.y, hv.y);
        }
        float2 vi = u2f2(a0), vf = u2f2(a1), vg = u2f2(a2), vo = u2f2(a3);
        float gi = vi.x + vi.y + p_i;
        float gf = vf.x + vf.y + p_f;
        float gg = vg.x + vg.y + p_g;
        float go = vo.x + vo.y + p_o;
        float iv = sigf(gi), fv = sigf(gf), zv = tanh_fast(gg), ov = sigf(go);
        c_state = fv * c_state + iv * zv;
        float h_val = ov * tanh_fast(c_state);

        snew[lane * 4 + jj] = h_val;

        int t_next = dir ? (t - 1) : (t + 1);
        if (step != TCON - 1) {
            const float* prn = pre + ((size_t)t_next * 32 + lane) * 1024 + j;
            p_i = prn[0]; p_f = prn[256]; p_g = prn[512]; p_o = prn[768];
        }

        __syncthreads();

        if (jj == 0) {
            float4 hv4 = *(const float4*)(snew + lane * 4);
            *(float4*)&hout[((size_t)t * 32 + lane) * 512 + foff + jg * 4] = hv4;
            __syncwarp();
            if (lane == 0) {
                red_rel_add(cntp, 1u);
                unsigned target = 64u * (unsigned)(step + 1);
                while (ld_acq(cntp) < target) {}
            }
        }
        __syncthreads();

        if (step != TCON - 1) {
            const float* base = hout + ((size_t)t * 32) * 512 + foff;
            float4 tmp[16];
#pragma unroll
            for (int i = 0; i < 16; i++) {
                int b = jj * 8 + (i >> 1);
                int j0 = (i & 1) * 128 + lane * 4;
                tmp[i] = *(const float4*)(base + (size_t)b * 512 + j0);
            }
#pragma unroll
            for (int i = 0; i < 16; i++) {
                int b = jj * 8 + (i >> 1);
                int j0 = (i & 1) * 128 + lane * 4;
                *(float4*)(shh + b * 268 + j0) = tmp[i];
            }
        }
        __syncthreads();
        t = t_next;
    }

    if (tid == 0) {
        unsigned old = atom_inc_acqrel(&g_ecnt[0]);
        if (old == 127u) {
            st_rlx(&g_cnt_f[0], 0u);
            st_rlx(&g_cnt_r[0], 0u);
            st_rlx(&g_ecnt[0], 0u);
        }
    }
}

// ---------------------------------------------------------------------------
// FC heads (split-k partials + deterministic reduce)
// ---------------------------------------------------------------------------
__global__ void __launch_bounds__(256) fc_main(const float* __restrict__ h,
                                               const float* __restrict__ w1,
                                               const float* __restrict__ w2) {
    extern __shared__ float sh[];
    int kc = blockIdx.x;
    int grp = blockIdx.y;
    int tid = threadIdx.x;
    int nl = tid >> 4, bb = tid & 15;
    int n = grp * 16 + nl;
    bool valid = (n < 190);
    const float* wrow = valid
        ? (n < 100 ? w1 + (size_t)n * 524288 : w2 + (size_t)(n - 100) * 524288)
        : w1;

    float ax = 0.f, ay = 0.f;
    for (int tt = 0; tt < 32; tt++) {
        int t = kc * 32 + tt;
        const float* slab = h + (size_t)t * 16384;
        __syncthreads();
        for (int i = tid; i < 4096; i += 256) {
            int b = i >> 7;
            int q = i & 127;
            float4 v = *(const float4*)&slab[b * 512 + q * 4];
            int bl = (b & 15) * 2 + (b >> 4);
            int f = q * 4;
            sh[(f + 0) * 32 + bl] = v.x;
            sh[(f + 1) * 32 + bl] = v.y;
            sh[(f + 2) * 32 + bl] = v.z;
            sh[(f + 3) * 32 + bl] = v.w;
        }
        __syncthreads();
        const float* wp = wrow + (size_t)t * 512;
#pragma unroll 4
        for (int f4 = 0; f4 < 128; f4++) {
            float4 wv = *(const float4*)(wp + f4 * 4);
            const float* s0 = sh + (f4 * 4) * 32 + bb * 2;
            float2 a0 = *(const float2*)(s0);
            float2 a1 = *(const float2*)(s0 + 32);
            float2 a2 = *(const float2*)(s0 + 64);
            float2 a3 = *(const float2*)(s0 + 96);
            ax = fmaf(wv.x, a0.x, ax); ay = fmaf(wv.x, a0.y, ay);
            ax = fmaf(wv.y, a1.x, ax); ay = fmaf(wv.y, a1.y, ay);
            ax = fmaf(wv.z, a2.x, ax); ay = fmaf(wv.z, a2.y, ay);
            ax = fmaf(wv.w, a3.x, ax); ay = fmaf(wv.w, a3.y, ay);
        }
    }
    if (valid) {
        g_fc_part[((size_t)kc * 192 + n) * 32 + bb] = ax;
        g_fc_part[((size_t)kc * 192 + n) * 32 + bb + 16] = ay;
    }
}

__global__ void fc_reduce(const float* __restrict__ b1,
                          const float* __restrict__ b2,
                          float* __restrict__ out) {
    int i = blockIdx.x * 256 + threadIdx.x;
    if (i >= 6080) return;
    int n = i >> 5;
    int b = i & 31;
    float s = (n < 100) ? b1[n] : b2[n - 100];
#pragma unroll
    for (int kc = 0; kc < 32; kc++)
        s += g_fc_part[((size_t)kc * 192 + n) * 32 + b];
    if (n < 100) out[b * 100 + n] = s;
    else out[3200 + b * 90 + (n - 100)] = s;
}

// ---------------------------------------------------------------------------
// Launch
// ---------------------------------------------------------------------------
extern "C" void kernel_launch(void* const* d_in, const int* in_sizes, int n_in,
                              void* d_out, int out_size) {
    const float* x       = (const float*)d_in[0];
    const float* conv_w  = (const float*)d_in[1];
    const float* conv_b  = (const float*)d_in[2];
    const float* bn_g    = (const float*)d_in[3];
    const float* bn_b    = (const float*)d_in[4];
    const float* bn_m    = (const float*)d_in[5];
    const float* bn_v    = (const float*)d_in[6];
    const float* w_ih_f0 = (const float*)d_in[7];
    const float* w_hh_f0 = (const float*)d_in[8];
    const float* b_f0    = (const float*)d_in[9];
    const float* w_ih_r0 = (const float*)d_in[10];
    const float* w_hh_r0 = (const float*)d_in[11];
    const float* b_r0    = (const float*)d_in[12];
    const float* w_ih_f1 = (const float*)d_in[13];
    const float* w_hh_f1 = (const float*)d_in[14];
    const float* b_f1    = (const float*)d_in[15];
    const float* w_ih_r1 = (const float*)d_in[16];
    const float* w_hh_r1 = (const float*)d_in[17];
    const float* b_r1    = (const float*)d_in[18];
    const float* fc1_w   = (const float*)d_in[19];
    const float* fc1_b   = (const float*)d_in[20];
    const float* fc2_w   = (const float*)d_in[21];
    const float* fc2_b   = (const float*)d_in[22];
    float* out = (float*)d_out;

    float *py, *ppf, *ppr, *ph0, *ph1;
    cudaGetSymbolAddress((void**)&py, g_y);
    cudaGetSymbolAddress((void**)&ppf, g_pre_f);
    cudaGetSymbolAddress((void**)&ppr, g_pre_r);
    cudaGetSymbolAddress((void**)&ph0, g_h0);
    cudaGetSymbolAddress((void**)&ph1, g_h1);

    cudaFuncSetAttribute(lstm_layer, cudaFuncAttributeMaxDynamicSharedMemorySize, LSTM_SMEM);
    cudaFuncSetAttribute(fc_main, cudaFuncAttributeMaxDynamicSharedMemorySize, 65536);

    // 1) conv + bn + relu
    conv_bn<<<32768, 256>>>(x, conv_w, conv_b, bn_g, bn_b, bn_m, bn_v);

    // 2) layer 0 input projections (K=256) — tensor cores, 3-pass bf16 split
    dim3 gg(16, 256);
    gemm_bf16x3<<<gg, 256>>>(py, w_ih_f0, b_f0, ppf, 256);
    gemm_bf16x3<<<gg, 256>>>(py, w_ih_r0, b_r0, ppr, 256);

    // 3) layer 0 recurrence (R11 config)
    lstm_layer<<<128, 128, LSTM_SMEM>>>(ppf, ppr, w_hh_f0, w_hh_r0, ph0);

    // 4) layer 1 input projections (K=512)
    gemm_bf16x3<<<gg, 256>>>(ph0, w_ih_f1, b_f1, ppf, 512);
    gemm_bf16x3<<<gg, 256>>>(ph0, w_ih_r1, b_r1, ppr, 512);

    // 5) layer 1 recurrence
    lstm_layer<<<128, 128, LSTM_SMEM>>>(ppf, ppr, w_hh_f1, w_hh_r1, ph1);

    // 6) FC heads
    dim3 fg(32, 12);
    fc_main<<<fg, 256, 65536>>>(ph1, fc1_w, fc2_w);
    fc_reduce<<<24, 256>>>(fc1_b, fc2_b, out);
}

// round 17
// speedup vs baseline: 1.2300x; 1.0035x over previous
#include <cuda_runtime.h>
#include <cuda_bf16.h>
#include <cstdint>

// ---------------------------------------------------------------------------
// Problem constants
//   B=32, T=2048, C=256, H=256, STRIDE=2, TC=1024, NC1=100, NC2=90
// ---------------------------------------------------------------------------
#define TCON 1024
typedef unsigned long long u64;

// LSTM smem: weights 16x256 = 4096 floats; h: 32x268 = 8576; stage: 128
#define LSTM_SW_FLOATS 4096
#define LSTM_SH_FLOATS (32 * 268)
#define LSTM_SN_OFF (LSTM_SW_FLOATS + LSTM_SH_FLOATS)
#define LSTM_SMEM ((LSTM_SW_FLOATS + LSTM_SH_FLOATS + 128) * 4)

// ---------------------------------------------------------------------------
// Scratch (device globals; no runtime allocation allowed)
// ---------------------------------------------------------------------------
__device__ float g_y[32768 * 256];
__device__ float g_pre_f[33554432];     // 32768*1024
__device__ float g_pre_r[33554432];
__device__ float g_h0[16777216];        // 32768*512
__device__ float g_h1[16777216];
__device__ float g_fc_part[64 * 192 * 32];
// bf16 hi/lo split buffers (A: max 16.8M elems for h0; W: max 524288)
__device__ __nv_bfloat16 g_ah[16777216];
__device__ __nv_bfloat16 g_al[16777216];
__device__ __nv_bfloat16 g_bhf[524288];
__device__ __nv_bfloat16 g_blf[524288];
__device__ __nv_bfloat16 g_bhr[524288];
__device__ __nv_bfloat16 g_blr[524288];
// Monotone step counters, one 128B line each (no false sharing between dirs).
__device__ __align__(128) unsigned int g_cnt_f[32];
__device__ __align__(128) unsigned int g_cnt_r[32];
__device__ __align__(128) unsigned int g_ecnt[32];

// ---------------------------------------------------------------------------
// Helpers
// ---------------------------------------------------------------------------
__device__ __forceinline__ void fma2(u64& acc, u64 a, u64 b) {
    asm("fma.rn.f32x2 %0, %1, %2, %0;" : "+l"(acc) : "l"(a), "l"(b));
}
__device__ __forceinline__ float2 u2f2(u64 v) {
    float2 r;
    asm("mov.b64 {%0,%1}, %2;" : "=f"(r.x), "=f"(r.y) : "l"(v));
    return r;
}
__device__ __forceinline__ float sigf(float x) {
    return __fdividef(1.f, 1.f + __expf(-x));
}
__device__ __forceinline__ float tanh_fast(float x) {
    return 2.f * sigf(2.f * x) - 1.f;
}
__device__ __forceinline__ unsigned ld_acq(const unsigned* p) {
    unsigned v;
    asm volatile("ld.acquire.gpu.global.u32 %0, [%1];" : "=r"(v) : "l"(p) : "memory");
    return v;
}
__device__ __forceinline__ void st_rlx(unsigned* p, unsigned v) {
    asm volatile("st.relaxed.gpu.global.u32 [%0], %1;" :: "l"(p), "r"(v) : "memory");
}
__device__ __forceinline__ void red_rel_add(unsigned* p, unsigned v) {
    asm volatile("red.release.gpu.global.add.u32 [%0], %1;" :: "l"(p), "r"(v) : "memory");
}
__device__ __forceinline__ unsigned atom_inc_acqrel(unsigned* p) {
    unsigned o;
    asm volatile("atom.add.acq_rel.gpu.global.u32 %0, [%1], 1;" : "=r"(o) : "l"(p) : "memory");
    return o;
}
__device__ __forceinline__ uint32_t smem_u32(const void* p) {
    uint32_t a;
    asm("{ .reg .u64 t; cvta.to.shared.u64 t, %1; cvt.u32.u64 %0, t; }"
        : "=r"(a) : "l"(p));
    return a;
}
__device__ __forceinline__ void ldm4(uint32_t& d0, uint32_t& d1, uint32_t& d2,
                                     uint32_t& d3, uint32_t addr) {
    asm volatile("ldmatrix.sync.aligned.m8n8.x4.shared.b16 {%0,%1,%2,%3}, [%4];"
                 : "=r"(d0), "=r"(d1), "=r"(d2), "=r"(d3) : "r"(addr));
}
__device__ __forceinline__ void mma_bf16(float* c, const uint32_t* a,
                                         uint32_t b0, uint32_t b1) {
    asm volatile(
        "mma.sync.aligned.m16n8k16.row.col.f32.bf16.bf16.f32 "
        "{%0,%1,%2,%3}, {%4,%5,%6,%7}, {%8,%9}, {%0,%1,%2,%3};"
        : "+f"(c[0]), "+f"(c[1]), "+f"(c[2]), "+f"(c[3])
        : "r"(a[0]), "r"(a[1]), "r"(a[2]), "r"(a[3]), "r"(b0), "r"(b1));
}

// ---------------------------------------------------------------------------
// fp32 -> (bf16 hi, bf16 lo) split, elementwise (vectorized by 4).
// ---------------------------------------------------------------------------
__global__ void cvt_split(const float* __restrict__ in,
                          __nv_bfloat16* __restrict__ hi,
                          __nv_bfloat16* __restrict__ lo, int n4) {
    int i = blockIdx.x * 256 + threadIdx.x;
    if (i >= n4) return;
    float4 v = ((const float4*)in)[i];
    float f[4] = {v.x, v.y, v.z, v.w};
    __nv_bfloat16 h[4], l[4];
#pragma unroll
    for (int e = 0; e < 4; e++) {
        h[e] = __float2bfloat16(f[e]);
        l[e] = __float2bfloat16(f[e] - __bfloat162float(h[e]));
    }
    __nv_bfloat162 h01, h23, l01, l23;
    h01.x = h[0]; h01.y = h[1]; h23.x = h[2]; h23.y = h[3];
    l01.x = l[0]; l01.y = l[1]; l23.x = l[2]; l23.y = l[3];
    *(__nv_bfloat162*)&hi[i * 4] = h01;
    *(__nv_bfloat162*)&hi[i * 4 + 2] = h23;
    *(__nv_bfloat162*)&lo[i * 4] = l01;
    *(__nv_bfloat162*)&lo[i * 4 + 2] = l23;
}

// ---------------------------------------------------------------------------
// Conv1d(k=3, stride=2, pad=1) + BN(affine, eval) + ReLU
// ---------------------------------------------------------------------------
__global__ void conv_bn(const float* __restrict__ x,
                        const float* __restrict__ cw,
                        const float* __restrict__ cb,
                        const float* __restrict__ gmm,
                        const float* __restrict__ bet,
                        const float* __restrict__ mean,
                        const float* __restrict__ var) {
    int tb = blockIdx.x;
    int t = tb >> 5, b = tb & 31;
    int c = threadIdx.x;
    float w0 = cw[c * 3 + 0], w1 = cw[c * 3 + 1], w2 = cw[c * 3 + 2];
    const float* xb = x + b * 2048;
    int xi = t * 2;
    float xm1 = (xi >= 1) ? xb[xi - 1] : 0.f;
    float x0 = xb[xi];
    float xp1 = xb[xi + 1];
    float conv = fmaf(xm1, w0, fmaf(x0, w1, xp1 * w2)) + cb[c];
    float inv = gmm[c] * rsqrtf(var[c] + 1e-5f);
    float v = conv * inv + (bet[c] - mean[c] * inv);
    g_y[(size_t)tb * 256 + c] = fmaxf(v, 0.f);
}

// ---------------------------------------------------------------------------
// Tensor-core GEMM (TN), 3-pass bf16 hi/lo from PRE-SPLIT arrays:
//   C[M][N=1024] = A[M][K] * B[N][K]^T + bias[N]
// Block tile 128x64xBK32, 256 threads, 8 warps (4x2), warp tile 32x32.
// Mainloop is pure LDG(bf16) -> STS -> ldmatrix -> mma (no conversions).
// SMEM rows padded to 40 bf16 (80 B) -> ldmatrix conflict-free.
// ---------------------------------------------------------------------------
#define GA_HI 0
#define GA_LO 5120
#define GB_HI 10240
#define GB_LO 12800

__global__ void __launch_bounds__(256) gemm_bf16v2(
        const __nv_bfloat16* __restrict__ Ah,
        const __nv_bfloat16* __restrict__ Al,
        const __nv_bfloat16* __restrict__ Bh,
        const __nv_bfloat16* __restrict__ Bl,
        const float* __restrict__ bias,
        float* __restrict__ C, int K) {
    __shared__ __align__(16) __nv_bfloat16 sm[15360];
    const int tid = threadIdx.x;
    const int bn = blockIdx.x * 64;
    const int bm = blockIdx.y * 128;
    const int lane = tid & 31;
    const int w = tid >> 5;
    const int wm = w >> 1, wn = w & 1;
    const uint32_t sbase = smem_u32(sm);

    float acc[2][4][4];
#pragma unroll
    for (int i = 0; i < 2; i++)
#pragma unroll
        for (int j = 0; j < 4; j++)
#pragma unroll
            for (int e = 0; e < 4; e++) acc[i][j][e] = 0.f;

    const int KIT = K >> 5;
    // A: 128 rows x 32 k, 8-elem (16B) groups; thread loads groups tid*2, tid*2+1
    const int ar = tid >> 1;                      // row 0..127
    const int ac0 = (tid & 1) * 2;                // group 0/2 then +1
    // B: 64 rows x 32 k; thread tid loads group tid (256 groups)
    const int br = tid >> 2;
    const int bc = tid & 3;

    uint4 rah0, rah1, ral0, ral1, rbh, rbl;
    {
        const size_t a_off = (size_t)(bm + ar) * K;
        rah0 = *(const uint4*)&Ah[a_off + ac0 * 8];
        rah1 = *(const uint4*)&Ah[a_off + (ac0 + 1) * 8];
        ral0 = *(const uint4*)&Al[a_off + ac0 * 8];
        ral1 = *(const uint4*)&Al[a_off + (ac0 + 1) * 8];
        const size_t b_off = (size_t)(bn + br) * K;
        rbh = *(const uint4*)&Bh[b_off + bc * 8];
        rbl = *(const uint4*)&Bl[b_off + bc * 8];
    }

    for (int it = 0; it < KIT; it++) {
        // ---- STS (pre-split bf16, no conversion) ----
        {
            int elA = ar * 40 + ac0 * 8;
            *(uint4*)&sm[GA_HI + elA] = rah0;
            *(uint4*)&sm[GA_HI + elA + 8] = rah1;
            *(uint4*)&sm[GA_LO + elA] = ral0;
            *(uint4*)&sm[GA_LO + elA + 8] = ral1;
            int elB = br * 40 + bc * 8;
            *(uint4*)&sm[GB_HI + elB] = rbh;
            *(uint4*)&sm[GB_LO + elB] = rbl;
        }
        __syncthreads();

        // prefetch next k-slab into regs (overlaps mma below)
        if (it + 1 < KIT) {
            int k0 = (it + 1) * 32;
            const size_t a_off = (size_t)(bm + ar) * K + k0;
            rah0 = *(const uint4*)&Ah[a_off + ac0 * 8];
            rah1 = *(const uint4*)&Ah[a_off + (ac0 + 1) * 8];
            ral0 = *(const uint4*)&Al[a_off + ac0 * 8];
            ral1 = *(const uint4*)&Al[a_off + (ac0 + 1) * 8];
            const size_t b_off = (size_t)(bn + br) * K + k0;
            rbh = *(const uint4*)&Bh[b_off + bc * 8];
            rbl = *(const uint4*)&Bl[b_off + bc * 8];
        }

        // ---- compute: 2 chunks of k16 ----
        const int mat = lane >> 3, mr = lane & 7;
#pragma unroll
        for (int ck = 0; ck < 2; ck++) {
            int kof = ck * 16;
            uint32_t ah[2][4], al[2][4], bh[2][4], bl[2][4];
#pragma unroll
            for (int mi = 0; mi < 2; mi++) {
                int row = wm * 32 + mi * 16 + ((mat & 1) * 8 + mr);
                int col = kof + ((mat >> 1) * 8);
                uint32_t off = (uint32_t)(row * 40 + col) * 2;
                ldm4(ah[mi][0], ah[mi][1], ah[mi][2], ah[mi][3],
                     sbase + GA_HI * 2 + off);
                ldm4(al[mi][0], al[mi][1], al[mi][2], al[mi][3],
                     sbase + GA_LO * 2 + off);
            }
#pragma unroll
            for (int p = 0; p < 2; p++) {
                int row = wn * 32 + p * 16 + ((mat >> 1) * 8 + mr);
                int col = kof + ((mat & 1) * 8);
                uint32_t off = (uint32_t)(row * 40 + col) * 2;
                ldm4(bh[p][0], bh[p][1], bh[p][2], bh[p][3],
                     sbase + GB_HI * 2 + off);
                ldm4(bl[p][0], bl[p][1], bl[p][2], bl[p][3],
                     sbase + GB_LO * 2 + off);
            }
#pragma unroll
            for (int mi = 0; mi < 2; mi++)
#pragma unroll
                for (int ni = 0; ni < 4; ni++) {
                    int p = ni >> 1, o = (ni & 1) * 2;
                    mma_bf16(acc[mi][ni], ah[mi], bh[p][o], bh[p][o + 1]);
                    mma_bf16(acc[mi][ni], ah[mi], bl[p][o], bl[p][o + 1]);
                    mma_bf16(acc[mi][ni], al[mi], bh[p][o], bh[p][o + 1]);
                }
        }
        __syncthreads();
    }

    // ---- epilogue ----
    const int g = lane >> 2, tg = lane & 3;
#pragma unroll
    for (int mi = 0; mi < 2; mi++)
#pragma unroll
        for (int ni = 0; ni < 4; ni++) {
            int m0 = bm + wm * 32 + mi * 16 + g;
            int n0 = bn + wn * 32 + ni * 8 + tg * 2;
            float b0 = bias[n0], b1 = bias[n0 + 1];
            float2 v0, v1;
            v0.x = acc[mi][ni][0] + b0; v0.y = acc[mi][ni][1] + b1;
            v1.x = acc[mi][ni][2] + b0; v1.y = acc[mi][ni][3] + b1;
            *(float2*)&C[(size_t)m0 * 1024 + n0] = v0;
            *(float2*)&C[(size_t)(m0 + 8) * 1024 + n0] = v1;
        }
}

// ---------------------------------------------------------------------------
// BiLSTM recurrence (one layer, both directions). R11 configuration verbatim.
// ---------------------------------------------------------------------------
__global__ void __launch_bounds__(128) lstm_layer(const float* __restrict__ pre_fw,
                                                  const float* __restrict__ pre_rv,
                                                  const float* __restrict__ whh_fw,
                                                  const float* __restrict__ whh_rv,
                                                  float* __restrict__ hout) {
    extern __shared__ float smem[];
    float* sw = smem;                      // [jj*4+g][256]
    float* shh = smem + LSTM_SW_FLOATS;    // [b][268]
    float* snew = smem + LSTM_SN_OFF;      // [b*4 + jj]

    const int tid = threadIdx.x;
    const int dir = blockIdx.x >> 6;
    const int jg = blockIdx.x & 63;
    const int jj = tid >> 5;               // warp id = local j
    const int lane = tid & 31;             // lane = batch
    const int j = jg * 4 + jj;
    const float* whh = dir ? whh_rv : whh_fw;
    const float* pre = dir ? pre_rv : pre_fw;
    const int foff = dir ? 256 : 0;

    for (int i = tid; i < 4096; i += 128) {
        int row = i >> 8;
        int k = i & 255;
        int ljj = row >> 2, g = row & 3;
        sw[row * 256 + k] = whh[((size_t)(g * 256 + jg * 4 + ljj)) * 256 + k];
    }
    for (int i = tid; i < LSTM_SH_FLOATS; i += 128) shh[i] = 0.f;
    __syncthreads();

    const float* hrow = shh + lane * 268;
    const float* wbase = sw + jj * 1024;

    unsigned* cntp = dir ? &g_cnt_r[0] : &g_cnt_f[0];

    float c_state = 0.f;
    int t = dir ? (TCON - 1) : 0;

    const float* pr0 = pre + ((size_t)t * 32 + lane) * 1024 + j;
    float p_i = pr0[0], p_f = pr0[256], p_g = pr0[512], p_o = pr0[768];

    for (int step = 0; step < TCON; step++) {
        u64 a0 = 0ull, a1 = 0ull, a2 = 0ull, a3 = 0ull;
#pragma unroll 2
        for (int k4 = 0; k4 < 64; k4++) {
            ulonglong2 hv = *(const ulonglong2*)(hrow + k4 * 4);
            ulonglong2 w0 = *(const ulonglong2*)(wbase + k4 * 4);
            ulonglong2 w1 = *(const ulonglong2*)(wbase + 256 + k4 * 4);
            ulonglong2 w2 = *(const ulonglong2*)(wbase + 512 + k4 * 4);
            ulonglong2 w3 = *(const ulonglong2*)(wbase + 768 + k4 * 4);
            fma2(a0, w0.x, hv.x); fma2(a0, w0.y, hv.y);
            fma2(a1, w1.x, hv.x); fma2(a1, w1.y, hv.y);
            fma2(a2, w2.x, hv.x); fma2(a2, w2.y, hv.y);
            fma2(a3, w3.x, hv.x); fma2(a3, w3.y, hv.y);
        }
        float2 vi = u2f2(a0), vf = u2f2(a1), vg = u2f2(a2), vo = u2f2(a3);
        float gi = vi.x + vi.y + p_i;
        float gf = vf.x + vf.y + p_f;
        float gg = vg.x + vg.y + p_g;
        float go = vo.x + vo.y + p_o;
        float iv = sigf(gi), fv = sigf(gf), zv = tanh_fast(gg), ov = sigf(go);
        c_state = fv * c_state + iv * zv;
        float h_val = ov * tanh_fast(c_state);

        snew[lane * 4 + jj] = h_val;

        int t_next = dir ? (t - 1) : (t + 1);
        if (step != TCON - 1) {
            const float* prn = pre + ((size_t)t_next * 32 + lane) * 1024 + j;
            p_i = prn[0]; p_f = prn[256]; p_g = prn[512]; p_o = prn[768];
        }

        __syncthreads();

        if (jj == 0) {
            float4 hv4 = *(const float4*)(snew + lane * 4);
            *(float4*)&hout[((size_t)t * 32 + lane) * 512 + foff + jg * 4] = hv4;
            __syncwarp();
            if (lane == 0) {
                red_rel_add(cntp, 1u);
                unsigned target = 64u * (unsigned)(step + 1);
                while (ld_acq(cntp) < target) {}
            }
        }
        __syncthreads();

        if (step != TCON - 1) {
            const float* base = hout + ((size_t)t * 32) * 512 + foff;
            float4 tmp[16];
#pragma unroll
            for (int i = 0; i < 16; i++) {
                int b = jj * 8 + (i >> 1);
                int j0 = (i & 1) * 128 + lane * 4;
                tmp[i] = *(const float4*)(base + (size_t)b * 512 + j0);
            }
#pragma unroll
            for (int i = 0; i < 16; i++) {
                int b = jj * 8 + (i >> 1);
                int j0 = (i & 1) * 128 + lane * 4;
                *(float4*)(shh + b * 268 + j0) = tmp[i];
            }
        }
        __syncthreads();
        t = t_next;
    }

    if (tid == 0) {
        unsigned old = atom_inc_acqrel(&g_ecnt[0]);
        if (old == 127u) {
            st_rlx(&g_cnt_f[0], 0u);
            st_rlx(&g_cnt_r[0], 0u);
            st_rlx(&g_ecnt[0], 0u);
        }
    }
}

// ---------------------------------------------------------------------------
// FC heads (split-k 64 chunks + deterministic reduce)
// ---------------------------------------------------------------------------
__global__ void __launch_bounds__(256) fc_main(const float* __restrict__ h,
                                               const float* __restrict__ w1,
                                               const float* __restrict__ w2) {
    extern __shared__ float sh[];
    int kc = blockIdx.x;                  // 0..63
    int grp = blockIdx.y;
    int tid = threadIdx.x;
    int nl = tid >> 4, bb = tid & 15;
    int n = grp * 16 + nl;
    bool valid = (n < 190);
    const float* wrow = valid
        ? (n < 100 ? w1 + (size_t)n * 524288 : w2 + (size_t)(n - 100) * 524288)
        : w1;

    float ax = 0.f, ay = 0.f;
    for (int tt = 0; tt < 16; tt++) {
        int t = kc * 16 + tt;
        const float* slab = h + (size_t)t * 16384;
        __syncthreads();
        for (int i = tid; i < 4096; i += 256) {
            int b = i >> 7;
            int q = i & 127;
            float4 v = *(const float4*)&slab[b * 512 + q * 4];
            int bl = (b & 15) * 2 + (b >> 4);
            int f = q * 4;
            sh[(f + 0) * 32 + bl] = v.x;
            sh[(f + 1) * 32 + bl] = v.y;
            sh[(f + 2) * 32 + bl] = v.z;
            sh[(f + 3) * 32 + bl] = v.w;
        }
        __syncthreads();
        const float* wp = wrow + (size_t)t * 512;
#pragma unroll 4
        for (int f4 = 0; f4 < 128; f4++) {
            float4 wv = *(const float4*)(wp + f4 * 4);
            const float* s0 = sh + (f4 * 4) * 32 + bb * 2;
            float2 a0 = *(const float2*)(s0);
            float2 a1 = *(const float2*)(s0 + 32);
            float2 a2 = *(const float2*)(s0 + 64);
            float2 a3 = *(const float2*)(s0 + 96);
            ax = fmaf(wv.x, a0.x, ax); ay = fmaf(wv.x, a0.y, ay);
            ax = fmaf(wv.y, a1.x, ax); ay = fmaf(wv.y, a1.y, ay);
            ax = fmaf(wv.z, a2.x, ax); ay = fmaf(wv.z, a2.y, ay);
            ax = fmaf(wv.w, a3.x, ax); ay = fmaf(wv.w, a3.y, ay);
        }
    }
    if (valid) {
        g_fc_part[((size_t)kc * 192 + n) * 32 + bb] = ax;
        g_fc_part[((size_t)kc * 192 + n) * 32 + bb + 16] = ay;
    }
}

__global__ void fc_reduce(const float* __restrict__ b1,
                          const float* __restrict__ b2,
                          float* __restrict__ out) {
    int i = blockIdx.x * 256 + threadIdx.x;
    if (i >= 6080) return;
    int n = i >> 5;
    int b = i & 31;
    float s = (n < 100) ? b1[n] : b2[n - 100];
#pragma unroll
    for (int kc = 0; kc < 64; kc++)
        s += g_fc_part[((size_t)kc * 192 + n) * 32 + b];
    if (n < 100) out[b * 100 + n] = s;
    else out[3200 + b * 90 + (n - 100)] = s;
}

// ---------------------------------------------------------------------------
// Launch
// ---------------------------------------------------------------------------
extern "C" void kernel_launch(void* const* d_in, const int* in_sizes, int n_in,
                              void* d_out, int out_size) {
    const float* x       = (const float*)d_in[0];
    const float* conv_w  = (const float*)d_in[1];
    const float* conv_b  = (const float*)d_in[2];
    const float* bn_g    = (const float*)d_in[3];
    const float* bn_b    = (const float*)d_in[4];
    const float* bn_m    = (const float*)d_in[5];
    const float* bn_v    = (const float*)d_in[6];
    const float* w_ih_f0 = (const float*)d_in[7];
    const float* w_hh_f0 = (const float*)d_in[8];
    const float* b_f0    = (const float*)d_in[9];
    const float* w_ih_r0 = (const float*)d_in[10];
    const float* w_hh_r0 = (const float*)d_in[11];
    const float* b_r0    = (const float*)d_in[12];
    const float* w_ih_f1 = (const float*)d_in[13];
    const float* w_hh_f1 = (const float*)d_in[14];
    const float* b_f1    = (const float*)d_in[15];
    const float* w_ih_r1 = (const float*)d_in[16];
    const float* w_hh_r1 = (const float*)d_in[17];
    const float* b_r1    = (const float*)d_in[18];
    const float* fc1_w   = (const float*)d_in[19];
    const float* fc1_b   = (const float*)d_in[20];
    const float* fc2_w   = (const float*)d_in[21];
    const float* fc2_b   = (const float*)d_in[22];
    float* out = (float*)d_out;

    float *py, *ppf, *ppr, *ph0, *ph1;
    __nv_bfloat16 *pah, *pal, *pbhf, *pblf, *pbhr, *pblr;
    cudaGetSymbolAddress((void**)&py, g_y);
    cudaGetSymbolAddress((void**)&ppf, g_pre_f);
    cudaGetSymbolAddress((void**)&ppr, g_pre_r);
    cudaGetSymbolAddress((void**)&ph0, g_h0);
    cudaGetSymbolAddress((void**)&ph1, g_h1);
    cudaGetSymbolAddress((void**)&pah, g_ah);
    cudaGetSymbolAddress((void**)&pal, g_al);
    cudaGetSymbolAddress((void**)&pbhf, g_bhf);
    cudaGetSymbolAddress((void**)&pblf, g_blf);
    cudaGetSymbolAddress((void**)&pbhr, g_bhr);
    cudaGetSymbolAddress((void**)&pblr, g_blr);

    cudaFuncSetAttribute(lstm_layer, cudaFuncAttributeMaxDynamicSharedMemorySize, LSTM_SMEM);
    cudaFuncSetAttribute(fc_main, cudaFuncAttributeMaxDynamicSharedMemorySize, 65536);

    // 1) conv + bn + relu
    conv_bn<<<32768, 256>>>(x, conv_w, conv_b, bn_g, bn_b, bn_m, bn_v);

    // 2) split-convert layer-0 operands, then tensor GEMMs (K=256)
    cvt_split<<<8192, 256>>>(py, pah, pal, 2097152);          // y: 8.39M elems
    cvt_split<<<256, 256>>>(w_ih_f0, pbhf, pblf, 65536);      // 262144 elems
    cvt_split<<<256, 256>>>(w_ih_r0, pbhr, pblr, 65536);
    dim3 gg(16, 256);
    gemm_bf16v2<<<gg, 256>>>(pah, pal, pbhf, pblf, b_f0, ppf, 256);
    gemm_bf16v2<<<gg, 256>>>(pah, pal, pbhr, pblr, b_r0, ppr, 256);

    // 3) layer 0 recurrence (R11 config)
    lstm_layer<<<128, 128, LSTM_SMEM>>>(ppf, ppr, w_hh_f0, w_hh_r0, ph0);

    // 4) split-convert layer-1 operands, then tensor GEMMs (K=512)
    cvt_split<<<16384, 256>>>(ph0, pah, pal, 4194304);        // h0: 16.8M elems
    cvt_split<<<512, 256>>>(w_ih_f1, pbhf, pblf, 131072);     // 524288 elems
    cvt_split<<<512, 256>>>(w_ih_r1, pbhr, pblr, 131072);
    gemm_bf16v2<<<gg, 256>>>(pah, pal, pbhf, pblf, b_f1, ppf, 512);
    gemm_bf16v2<<<gg, 256>>>(pah, pal, pbhr, pblr, b_r1, ppr, 512);

    // 5) layer 1 recurrence
    lstm_layer<<<128, 128, LSTM_SMEM>>>(ppf, ppr, w_hh_f1, w_hh_r1, ph1);

    // 6) FC heads (64-way split-k)
    dim3 fg(64, 12);
    fc_main<<<fg, 256, 65536>>>(ph1, fc1_w, fc2_w);
    fc_reduce<<<24, 256>>>(fc1_b, fc2_b, out);
}